// round 8
// baseline (speedup 1.0000x reference)
#include <cuda_runtime.h>
#include <math.h>
#include <stdint.h>

#define NN 50000
#define EE 800000
#define CC 64

typedef unsigned long long ull;

// ---------------- scratch ----------------
__device__ float  g_m[NN * CC];          // x @ W
__device__ float  g_p1[NN * CC];         // m @ Wpre[0:64]   (dst term)
__device__ float  g_p2[NN * CC];         // m @ Wpre[64:128] (src term)
__device__ float  g_C3[3 * CC];          // We @ Wpre[128:192]
__device__ float  g_c3[CC];              // be @ Wpre[128:192]
__device__ int    g_cnt_i[NN];
__device__ int    g_off[NN + 1];
__device__ int    g_cur[NN];
__device__ int    g_srcp[EE];            // CSR-ordered src node
__device__ float4 g_attrp[EE];           // CSR-ordered edge_attr
__device__ float  g_agg[NN * 4 * CC];    // [mean | min | max | std]
__device__ float  g_a[NN];
__device__ float  g_ia[NN];
__device__ float  g_out_node[NN * CC];
__device__ float  g_gi[NN * 3 * CC];
__device__ float  g_gh[NN * 3 * CC];
__device__ float  g_avgsum[1];

// ---------------- packed f32x2 helpers ----------------
__device__ __forceinline__ ull pack2(float lo, float hi) {
    ull r;
    asm("mov.b64 %0, {%1, %2};" : "=l"(r) : "f"(lo), "f"(hi));
    return r;
}
__device__ __forceinline__ void unpack2(ull v, float& lo, float& hi) {
    asm("mov.b64 {%0, %1}, %2;" : "=f"(lo), "=f"(hi) : "l"(v));
}
__device__ __forceinline__ void fma2(ull& d, ull a, ull b) {
    asm("fma.rn.f32x2 %0, %1, %2, %0;" : "+l"(d) : "l"(a), "l"(b));
}

// ---------------- init ----------------
__global__ void init_kernel(int N) {
    int idx = blockIdx.x * 256 + threadIdx.x;
    if (idx < N) g_cnt_i[idx] = 0;
    if (idx == 0) g_avgsum[0] = 0.f;
}

// ---------------- avg_log ----------------
__global__ void avglog_kernel(const float* __restrict__ deg_hist, int N) {
    int idx = blockIdx.x * 256 + threadIdx.x;
    float v = (idx < N) ? logf(deg_hist[idx] + 1.f) : 0.f;
    #pragma unroll
    for (int o = 16; o; o >>= 1) v += __shfl_down_sync(0xFFFFFFFFu, v, o);
    __shared__ float sred[8];
    if ((threadIdx.x & 31) == 0) sred[threadIdx.x >> 5] = v;
    __syncthreads();
    if (threadIdx.x < 8) {
        v = sred[threadIdx.x];
        #pragma unroll
        for (int o = 4; o; o >>= 1) v += __shfl_down_sync(0xFFu, v, o);
        if (threadIdx.x == 0) atomicAdd(&g_avgsum[0], v);
    }
}

// ---------------- CSR build ----------------
__global__ void count_kernel(const int* __restrict__ edge_index, int E) {
    int idx = blockIdx.x * 256 + threadIdx.x;
    if (idx < E) atomicAdd(&g_cnt_i[edge_index[E + idx]], 1);
}

__global__ void __launch_bounds__(1024) scan_kernel(int N, int E) {
    __shared__ int sh[1024];
    int tid = threadIdx.x;
    int per = (N + 1023) / 1024;
    int start = tid * per;
    int end = start + per; if (end > N) end = N;
    int s = 0;
    for (int i = start; i < end; i++) s += g_cnt_i[i];
    sh[tid] = s;
    __syncthreads();
    for (int d = 1; d < 1024; d <<= 1) {
        int v = (tid >= d) ? sh[tid - d] : 0;
        __syncthreads();
        sh[tid] += v;
        __syncthreads();
    }
    int running = sh[tid] - s;
    for (int i = start; i < end; i++) {
        g_off[i] = running;
        g_cur[i] = running;
        running += g_cnt_i[i];
    }
    if (tid == 1023) g_off[N] = E;
}

// scatter edge payload into CSR order: removes indirection from the reduce loop
__global__ void scatter_kernel(const int* __restrict__ edge_index,
                               const float* __restrict__ edge_attr, int E) {
    int idx = blockIdx.x * 256 + threadIdx.x;
    if (idx < E) {
        int d = edge_index[E + idx];
        int pos = atomicAdd(&g_cur[d], 1);
        g_srcp[pos] = edge_index[idx];
        g_attrp[pos] = *reinterpret_cast<const float4*>(&edge_attr[(size_t)idx * 4]);
    }
}

// ---------------- prep: C3 = We @ Wpre3, c3 = be @ Wpre3 ----------------
__global__ void prep_kernel(const float* __restrict__ We, const float* __restrict__ be,
                            const float* __restrict__ Wpre) {
    int t = threadIdx.x;       // 0..255
    int r = t >> 6;            // 0..2 -> C3 rows, 3 -> c3
    int c = t & 63;
    const float* W3 = Wpre + 128 * 64;
    const float* vsrc = (r < 3) ? (We + r * 64) : be;
    float s = 0.f;
    #pragma unroll 8
    for (int j = 0; j < 64; j++) s += vsrc[j] * W3[j * 64 + c];
    if (r < 3) g_C3[r * 64 + c] = s;
    else       g_c3[c] = s;
}

// ---------------- double-buffered SGEMM: BM=128, BN=64, BK=32, 256 threads ----------------
__global__ void __launch_bounds__(256) gemm256(const float* __restrict__ A,
                                               const float* __restrict__ B,
                                               const float* __restrict__ bias,
                                               float* __restrict__ Cout,
                                               int M, int Ncol, int K) {
    __shared__ float As[2][32][128];
    __shared__ ull   Bs[2][32][32];
    int tid = threadIdx.x;
    int lane = tid & 31;
    int cg = tid >> 5;
    int mBase = blockIdx.y * 128;
    int nBase = blockIdx.x * 64;
    ull acc[4][4];
    #pragma unroll
    for (int e = 0; e < 4; e++)
        #pragma unroll
        for (int j = 0; j < 4; j++) acc[e][j] = 0ull;

    int ar = tid & 127;
    int ak = (tid >> 7) * 16;          // 0 or 16
    int brow = tid / 8;                // 0..31
    int bq = tid % 8;                  // 8 floats each
    int bcol = bq * 8;
    int m = mBase + ar;

    float4 av[4];
    float4 b0, b1;
    // prologue: tile 0
    #pragma unroll
    for (int q = 0; q < 4; q++) av[q] = make_float4(0.f, 0.f, 0.f, 0.f);
    if (m < M) {
        const float* ap = &A[(size_t)m * K + ak];
        #pragma unroll
        for (int q = 0; q < 4; q++) av[q] = *reinterpret_cast<const float4*>(ap + q * 4);
    }
    {
        const float* bp = &B[(size_t)brow * Ncol + nBase + bcol];
        b0 = *reinterpret_cast<const float4*>(bp);
        b1 = *reinterpret_cast<const float4*>(bp + 4);
    }

    int nk = K / 32;
    #pragma unroll 1
    for (int it = 0; it < nk; it++) {
        int buf = it & 1;
        #pragma unroll
        for (int q = 0; q < 4; q++) {
            As[buf][ak + q * 4 + 0][ar] = av[q].x;
            As[buf][ak + q * 4 + 1][ar] = av[q].y;
            As[buf][ak + q * 4 + 2][ar] = av[q].z;
            As[buf][ak + q * 4 + 3][ar] = av[q].w;
        }
        Bs[buf][brow][bq * 4 + 0] = pack2(b0.x, b0.y);
        Bs[buf][brow][bq * 4 + 1] = pack2(b0.z, b0.w);
        Bs[buf][brow][bq * 4 + 2] = pack2(b1.x, b1.y);
        Bs[buf][brow][bq * 4 + 3] = pack2(b1.z, b1.w);
        __syncthreads();
        if (it + 1 < nk) {
            int k0 = (it + 1) * 32;
            #pragma unroll
            for (int q = 0; q < 4; q++) av[q] = make_float4(0.f, 0.f, 0.f, 0.f);
            if (m < M) {
                const float* ap = &A[(size_t)m * K + k0 + ak];
                #pragma unroll
                for (int q = 0; q < 4; q++)
                    av[q] = *reinterpret_cast<const float4*>(ap + q * 4);
            }
            const float* bp = &B[(size_t)(k0 + brow) * Ncol + nBase + bcol];
            b0 = *reinterpret_cast<const float4*>(bp);
            b1 = *reinterpret_cast<const float4*>(bp + 4);
        }
        #pragma unroll
        for (int k = 0; k < 32; k++) {
            float4 a = *reinterpret_cast<const float4*>(&As[buf][k][lane * 4]);
            longlong2 p01 = *reinterpret_cast<const longlong2*>(&Bs[buf][k][cg * 4]);
            longlong2 p23 = *reinterpret_cast<const longlong2*>(&Bs[buf][k][cg * 4 + 2]);
            ull bp4[4] = {(ull)p01.x, (ull)p01.y, (ull)p23.x, (ull)p23.y};
            ull ad[4] = {pack2(a.x, a.x), pack2(a.y, a.y), pack2(a.z, a.z), pack2(a.w, a.w)};
            #pragma unroll
            for (int e = 0; e < 4; e++)
                #pragma unroll
                for (int j = 0; j < 4; j++) fma2(acc[e][j], ad[e], bp4[j]);
        }
        __syncthreads();
    }

    float bs[8] = {0, 0, 0, 0, 0, 0, 0, 0};
    if (bias) {
        float4 t0 = *reinterpret_cast<const float4*>(&bias[nBase + cg * 8]);
        float4 t1 = *reinterpret_cast<const float4*>(&bias[nBase + cg * 8 + 4]);
        bs[0] = t0.x; bs[1] = t0.y; bs[2] = t0.z; bs[3] = t0.w;
        bs[4] = t1.x; bs[5] = t1.y; bs[6] = t1.z; bs[7] = t1.w;
    }
    #pragma unroll
    for (int e = 0; e < 4; e++) {
        int mm = mBase + lane * 4 + e;
        if (mm < M) {
            float v[8];
            #pragma unroll
            for (int j = 0; j < 4; j++) unpack2(acc[e][j], v[2 * j], v[2 * j + 1]);
            float* cp = &Cout[(size_t)mm * Ncol + nBase + cg * 8];
            *reinterpret_cast<float4*>(cp) =
                make_float4(v[0] + bs[0], v[1] + bs[1], v[2] + bs[2], v[3] + bs[3]);
            *reinterpret_cast<float4*>(cp + 4) =
                make_float4(v[4] + bs[4], v[5] + bs[5], v[6] + bs[6], v[7] + bs[7]);
        }
    }
}

// ---------------- fused edge compute + node reduce: 2 warps per node ----------------
__global__ void __launch_bounds__(256) node_edge_reduce(const float* __restrict__ bpre,
                                                        int N) {
    int gw = blockIdx.x * 8 + (threadIdx.x >> 5);
    int n = gw >> 1;
    int half = gw & 1;
    if (n >= N) return;
    int lane = threadIdx.x & 31;
    int ch = half * 32 + lane;

    int off0 = g_off[n], off1 = g_off[n + 1];
    int deg = off1 - off0;

    float base = g_p1[(size_t)n * 64 + ch] + g_c3[ch];
    float c30 = g_C3[ch], c31 = g_C3[64 + ch], c32 = g_C3[128 + ch];
    float bp = bpre[ch];

    float s1 = 0.f, s2 = 0.f;
    float mn = 3.4e38f, mx = -3.4e38f;

    // pipeline: va one ahead, src/attr two ahead
    int src1 = 0;
    float4 at0 = make_float4(0.f, 0.f, 0.f, 0.f), at1 = at0;
    float va0 = 0.f;
    if (deg > 0) {
        int s0 = g_srcp[off0];
        at0 = g_attrp[off0];
        va0 = g_p2[(size_t)s0 * 64 + ch];
    }
    if (deg > 1) {
        src1 = g_srcp[off0 + 1];
        at1 = g_attrp[off0 + 1];
    }
    for (int i = off0; i < off1; i++) {
        float va = va0;
        float4 at = at0;
        if (i + 1 < off1) {
            va0 = g_p2[(size_t)src1 * 64 + ch];
            at0 = at1;
            if (i + 2 < off1) {
                src1 = g_srcp[i + 2];
                at1 = g_attrp[i + 2];
            }
        }
        float h = at.w * (base + va + at.x * c30 + at.y * c31 + at.z * c32) + bp;
        s1 += h; s2 += h * h;
        mn = fminf(mn, h); mx = fmaxf(mx, h);
    }

    float cnt = (float)deg;
    float safe = fmaxf(cnt, 1.f);
    float inv = 1.f / safe;
    float mean = s1 * inv;
    float stdv = sqrtf(fmaxf(s2 * inv - mean * mean, 0.f) + 1e-5f);
    if (deg == 0) { mn = 0.f; mx = 0.f; }
    size_t b = (size_t)n * 256 + ch;
    g_agg[b]       = mean;
    g_agg[b + 64]  = mn;
    g_agg[b + 128] = mx;
    g_agg[b + 192] = stdv;
    if (ch == 0) {
        float avg = g_avgsum[0] / (float)N;
        float logd = logf(safe + 1.f);
        float a = logd / avg;
        g_a[n]  = a;
        g_ia[n] = a * (avg / logd);   // fp-composed o3 scale
    }
}

// ---------------- Wpost GEMM (K=832), on-the-fly z, BK=32 double-buffered ----------------
__global__ void __launch_bounds__(256) gemm_post(const float* __restrict__ Wpost,
                                                 const float* __restrict__ bpost, int M) {
    __shared__ float As[2][32][128];
    __shared__ ull   Bs[2][32][32];
    int tid = threadIdx.x;
    int lane = tid & 31;
    int cg = tid >> 5;
    int mBase = blockIdx.x * 128;
    ull acc[4][4];
    #pragma unroll
    for (int e = 0; e < 4; e++)
        #pragma unroll
        for (int j = 0; j < 4; j++) acc[e][j] = 0ull;

    int ar = tid & 127;
    int ak = (tid >> 7) * 16;
    int brow = tid / 8;
    int bq = tid % 8;
    int bcol = bq * 8;
    int m = mBase + ar;
    float sa = 0.f, sia = 0.f;
    if (m < M) { sa = g_a[m]; sia = g_ia[m]; }

    float4 av[4];
    float4 b0, b1;
    // z-row loader for k in [k0+ak, k0+ak+16)
    auto loadA = [&](int k0) {
        #pragma unroll
        for (int q = 0; q < 4; q++) av[q] = make_float4(0.f, 0.f, 0.f, 0.f);
        if (m < M) {
            #pragma unroll
            for (int q = 0; q < 4; q++) {
                int k = k0 + ak + q * 4;
                float sc = 1.f;
                const float* src;
                if (k < 64)       src = &g_m[(size_t)m * 64 + k];
                else if (k < 320) src = &g_agg[(size_t)m * 256 + (k - 64)];
                else if (k < 576) { src = &g_agg[(size_t)m * 256 + (k - 320)]; sc = sa; }
                else              { src = &g_agg[(size_t)m * 256 + (k - 576)]; sc = sia; }
                float4 t = *reinterpret_cast<const float4*>(src);
                t.x *= sc; t.y *= sc; t.z *= sc; t.w *= sc;
                av[q] = t;
            }
        }
    };

    loadA(0);
    {
        const float* bp = &Wpost[(size_t)brow * 64 + bcol];
        b0 = *reinterpret_cast<const float4*>(bp);
        b1 = *reinterpret_cast<const float4*>(bp + 4);
    }

    const int nk = 832 / 32;
    #pragma unroll 1
    for (int it = 0; it < nk; it++) {
        int buf = it & 1;
        #pragma unroll
        for (int q = 0; q < 4; q++) {
            As[buf][ak + q * 4 + 0][ar] = av[q].x;
            As[buf][ak + q * 4 + 1][ar] = av[q].y;
            As[buf][ak + q * 4 + 2][ar] = av[q].z;
            As[buf][ak + q * 4 + 3][ar] = av[q].w;
        }
        Bs[buf][brow][bq * 4 + 0] = pack2(b0.x, b0.y);
        Bs[buf][brow][bq * 4 + 1] = pack2(b0.z, b0.w);
        Bs[buf][brow][bq * 4 + 2] = pack2(b1.x, b1.y);
        Bs[buf][brow][bq * 4 + 3] = pack2(b1.z, b1.w);
        __syncthreads();
        if (it + 1 < nk) {
            int k0 = (it + 1) * 32;
            loadA(k0);
            const float* bp = &Wpost[(size_t)(k0 + brow) * 64 + bcol];
            b0 = *reinterpret_cast<const float4*>(bp);
            b1 = *reinterpret_cast<const float4*>(bp + 4);
        }
        #pragma unroll
        for (int k = 0; k < 32; k++) {
            float4 a = *reinterpret_cast<const float4*>(&As[buf][k][lane * 4]);
            longlong2 p01 = *reinterpret_cast<const longlong2*>(&Bs[buf][k][cg * 4]);
            longlong2 p23 = *reinterpret_cast<const longlong2*>(&Bs[buf][k][cg * 4 + 2]);
            ull bp4[4] = {(ull)p01.x, (ull)p01.y, (ull)p23.x, (ull)p23.y};
            ull ad[4] = {pack2(a.x, a.x), pack2(a.y, a.y), pack2(a.z, a.z), pack2(a.w, a.w)};
            #pragma unroll
            for (int e = 0; e < 4; e++)
                #pragma unroll
                for (int j = 0; j < 4; j++) fma2(acc[e][j], ad[e], bp4[j]);
        }
        __syncthreads();
    }

    float4 t0 = *reinterpret_cast<const float4*>(&bpost[cg * 8]);
    float4 t1 = *reinterpret_cast<const float4*>(&bpost[cg * 8 + 4]);
    float bs[8] = {t0.x, t0.y, t0.z, t0.w, t1.x, t1.y, t1.z, t1.w};
    #pragma unroll
    for (int e = 0; e < 4; e++) {
        int mm = mBase + lane * 4 + e;
        if (mm < M) {
            float v[8];
            #pragma unroll
            for (int j = 0; j < 4; j++) unpack2(acc[e][j], v[2 * j], v[2 * j + 1]);
            float* cp = &g_out_node[(size_t)mm * 64 + cg * 8];
            *reinterpret_cast<float4*>(cp) =
                make_float4(v[0] + bs[0], v[1] + bs[1], v[2] + bs[2], v[3] + bs[3]);
            *reinterpret_cast<float4*>(cp + 4) =
                make_float4(v[4] + bs[4], v[5] + bs[5], v[6] + bs[6], v[7] + bs[7]);
        }
    }
}

// ---------------- GRU elementwise ----------------
__global__ void gru_kernel(const float* __restrict__ x, float* __restrict__ out, int N) {
    int idx = blockIdx.x * 256 + threadIdx.x;
    if (idx >= N * CC) return;
    int n = idx >> 6, c = idx & 63;
    size_t b = (size_t)n * 192;
    float ir = g_gi[b + c],        hr = g_gh[b + c];
    float iz = g_gi[b + 64 + c],   hz = g_gh[b + 64 + c];
    float in_ = g_gi[b + 128 + c], hn = g_gh[b + 128 + c];
    float r = 1.f / (1.f + expf(-(ir + hr)));
    float z = 1.f / (1.f + expf(-(iz + hz)));
    float nn = tanhf(in_ + r * hn);
    out[idx] = (1.f - z) * nn + z * x[idx];
}

// ---------------- launch ----------------
extern "C" void kernel_launch(void* const* d_in, const int* in_sizes, int n_in,
                              void* d_out, int out_size) {
    const float* x         = (const float*)d_in[0];
    const float* edge_attr = (const float*)d_in[1];
    const float* deg_hist  = (const float*)d_in[2];
    const float* W         = (const float*)d_in[3];
    const float* We        = (const float*)d_in[4];
    const float* be        = (const float*)d_in[5];
    const float* Wpre      = (const float*)d_in[6];
    const float* bpre      = (const float*)d_in[7];
    const float* Wpost     = (const float*)d_in[8];
    const float* bpost     = (const float*)d_in[9];
    const float* Wih       = (const float*)d_in[10];
    const float* bih       = (const float*)d_in[11];
    const float* Whh       = (const float*)d_in[12];
    const float* bhh       = (const float*)d_in[13];
    const int*   edge_index = (const int*)d_in[14];

    int N = in_sizes[0] / CC;
    int E = in_sizes[14] / 2;

    float *pm, *pp1, *pp2, *pon, *pgi, *pgh;
    cudaGetSymbolAddress((void**)&pm,  g_m);
    cudaGetSymbolAddress((void**)&pp1, g_p1);
    cudaGetSymbolAddress((void**)&pp2, g_p2);
    cudaGetSymbolAddress((void**)&pon, g_out_node);
    cudaGetSymbolAddress((void**)&pgi, g_gi);
    cudaGetSymbolAddress((void**)&pgh, g_gh);

    int nodeElems = N * CC;
    int mBlocks = (N + 127) / 128;
    int eBlocks256 = (E + 255) / 256;

    init_kernel<<<(N + 255) / 256, 256>>>(N);
    avglog_kernel<<<(N + 255) / 256, 256>>>(deg_hist, N);
    count_kernel<<<eBlocks256, 256>>>(edge_index, E);
    prep_kernel<<<1, 256>>>(We, be, Wpre);
    gemm256<<<dim3(1, mBlocks), 256>>>(x, W, nullptr, pm, N, 64, 64);
    scan_kernel<<<1, 1024>>>(N, E);
    scatter_kernel<<<eBlocks256, 256>>>(edge_index, edge_attr, E);
    gemm256<<<dim3(1, mBlocks), 256>>>(pm, Wpre, nullptr, pp1, N, 64, 64);
    gemm256<<<dim3(1, mBlocks), 256>>>(pm, Wpre + 64 * 64, nullptr, pp2, N, 64, 64);
    node_edge_reduce<<<(2 * N + 7) / 8, 256>>>(bpre, N);
    gemm_post<<<mBlocks, 256>>>(Wpost, bpost, N);
    gemm256<<<dim3(3, mBlocks), 256>>>(pon, Wih, bih, pgi, N, 192, 64);
    gemm256<<<dim3(3, mBlocks), 256>>>(x, Whh, bhh, pgh, N, 192, 64);
    gru_kernel<<<(nodeElems + 255) / 256, 256>>>(x, (float*)d_out, N);
}

// round 9
// speedup vs baseline: 1.0158x; 1.0158x over previous
#include <cuda_runtime.h>
#include <math.h>
#include <stdint.h>

#define NN 50000
#define EE 800000
#define CC 64

typedef unsigned long long ull;

// ---------------- scratch ----------------
__device__ float  g_m[NN * CC];          // x @ W
__device__ float  g_p1[NN * CC];         // m @ Wpre[0:64]   (dst term)
__device__ float  g_p2[NN * CC];         // m @ Wpre[64:128] (src term)
__device__ float  g_C3[3 * CC];          // We @ Wpre[128:192]
__device__ float  g_c3[CC];              // be @ Wpre[128:192]
__device__ int    g_cnt_i[NN];
__device__ int    g_off[NN + 1];
__device__ int    g_cur[NN];
__device__ int    g_srcp[EE];            // CSR-ordered src node
__device__ float4 g_attrp[EE];           // CSR-ordered edge_attr
__device__ float  g_agg[NN * 4 * CC];    // [mean | min | max | std]
__device__ float  g_a[NN];
__device__ float  g_ia[NN];
__device__ float  g_out_node[NN * CC];
__device__ float  g_gi[NN * 3 * CC];
__device__ float  g_gh[NN * 3 * CC];
__device__ float  g_avgsum[1];

// ---------------- packed f32x2 helpers ----------------
__device__ __forceinline__ ull pack2(float lo, float hi) {
    ull r;
    asm("mov.b64 %0, {%1, %2};" : "=l"(r) : "f"(lo), "f"(hi));
    return r;
}
__device__ __forceinline__ void unpack2(ull v, float& lo, float& hi) {
    asm("mov.b64 {%0, %1}, %2;" : "=f"(lo), "=f"(hi) : "l"(v));
}
__device__ __forceinline__ void fma2(ull& d, ull a, ull b) {
    asm("fma.rn.f32x2 %0, %1, %2, %0;" : "+l"(d) : "l"(a), "l"(b));
}

// ---------------- init ----------------
__global__ void init_kernel(int N) {
    int idx = blockIdx.x * 256 + threadIdx.x;
    if (idx < N) g_cnt_i[idx] = 0;
    if (idx == 0) g_avgsum[0] = 0.f;
}

// ---------------- avg_log ----------------
__global__ void avglog_kernel(const float* __restrict__ deg_hist, int N) {
    int idx = blockIdx.x * 256 + threadIdx.x;
    float v = (idx < N) ? logf(deg_hist[idx] + 1.f) : 0.f;
    #pragma unroll
    for (int o = 16; o; o >>= 1) v += __shfl_down_sync(0xFFFFFFFFu, v, o);
    __shared__ float sred[8];
    if ((threadIdx.x & 31) == 0) sred[threadIdx.x >> 5] = v;
    __syncthreads();
    if (threadIdx.x < 8) {
        v = sred[threadIdx.x];
        #pragma unroll
        for (int o = 4; o; o >>= 1) v += __shfl_down_sync(0xFFu, v, o);
        if (threadIdx.x == 0) atomicAdd(&g_avgsum[0], v);
    }
}

// ---------------- CSR build ----------------
__global__ void count_kernel(const int* __restrict__ edge_index, int E) {
    int idx = blockIdx.x * 256 + threadIdx.x;
    if (idx < E) atomicAdd(&g_cnt_i[edge_index[E + idx]], 1);
}

__global__ void __launch_bounds__(1024) scan_kernel(int N, int E) {
    __shared__ int sh[1024];
    int tid = threadIdx.x;
    int per = (N + 1023) / 1024;
    int start = tid * per;
    int end = start + per; if (end > N) end = N;
    int s = 0;
    for (int i = start; i < end; i++) s += g_cnt_i[i];
    sh[tid] = s;
    __syncthreads();
    for (int d = 1; d < 1024; d <<= 1) {
        int v = (tid >= d) ? sh[tid - d] : 0;
        __syncthreads();
        sh[tid] += v;
        __syncthreads();
    }
    int running = sh[tid] - s;
    for (int i = start; i < end; i++) {
        g_off[i] = running;
        g_cur[i] = running;
        running += g_cnt_i[i];
    }
    if (tid == 1023) g_off[N] = E;
}

// scatter edge payload into CSR order
__global__ void scatter_kernel(const int* __restrict__ edge_index,
                               const float* __restrict__ edge_attr, int E) {
    int idx = blockIdx.x * 256 + threadIdx.x;
    if (idx < E) {
        int d = edge_index[E + idx];
        int pos = atomicAdd(&g_cur[d], 1);
        g_srcp[pos] = edge_index[idx];
        g_attrp[pos] = *reinterpret_cast<const float4*>(&edge_attr[(size_t)idx * 4]);
    }
}

// ---------------- prep: C3 = We @ Wpre3, c3 = be @ Wpre3 ----------------
__global__ void prep_kernel(const float* __restrict__ We, const float* __restrict__ be,
                            const float* __restrict__ Wpre) {
    int t = threadIdx.x;
    int r = t >> 6;
    int c = t & 63;
    const float* W3 = Wpre + 128 * 64;
    const float* vsrc = (r < 3) ? (We + r * 64) : be;
    float s = 0.f;
    #pragma unroll 8
    for (int j = 0; j < 64; j++) s += vsrc[j] * W3[j * 64 + c];
    if (r < 3) g_C3[r * 64 + c] = s;
    else       g_c3[c] = s;
}

// ---------------- shared GEMM core: BM=128, BN=64, BK=16, 256 thr, double-buffered ----------------
__device__ __forceinline__ void gemm_core16(const float* __restrict__ A,
                                            const float* __restrict__ B,
                                            const float* __restrict__ bias,
                                            float* __restrict__ Cout,
                                            int M, int Ncol, int K,
                                            int mBase, int nBase) {
    __shared__ float As[2][16][128];
    __shared__ ull   Bs[2][16][32];
    int tid = threadIdx.x;
    int lane = tid & 31;
    int cg = tid >> 5;
    ull acc[4][4];
    #pragma unroll
    for (int e = 0; e < 4; e++)
        #pragma unroll
        for (int j = 0; j < 4; j++) acc[e][j] = 0ull;

    int ar = tid & 127;
    int ak = (tid >> 7) * 8;
    int brow = tid / 16;
    int bp_idx = (tid % 16) * 2;
    int bcol = (tid % 16) * 4;
    int m = mBase + ar;

    float4 a0 = make_float4(0.f, 0.f, 0.f, 0.f), a1 = a0;
    if (m < M) {
        const float* ap = &A[(size_t)m * K + ak];
        a0 = *reinterpret_cast<const float4*>(ap);
        a1 = *reinterpret_cast<const float4*>(ap + 4);
    }
    float4 bv = *reinterpret_cast<const float4*>(&B[(size_t)brow * Ncol + nBase + bcol]);

    int nk = K / 16;
    #pragma unroll 1
    for (int it = 0; it < nk; it++) {
        int buf = it & 1;
        As[buf][ak + 0][ar] = a0.x; As[buf][ak + 1][ar] = a0.y;
        As[buf][ak + 2][ar] = a0.z; As[buf][ak + 3][ar] = a0.w;
        As[buf][ak + 4][ar] = a1.x; As[buf][ak + 5][ar] = a1.y;
        As[buf][ak + 6][ar] = a1.z; As[buf][ak + 7][ar] = a1.w;
        Bs[buf][brow][bp_idx]     = pack2(bv.x, bv.y);
        Bs[buf][brow][bp_idx + 1] = pack2(bv.z, bv.w);
        __syncthreads();
        if (it + 1 < nk) {
            int k0 = (it + 1) * 16;
            a0 = make_float4(0.f, 0.f, 0.f, 0.f); a1 = a0;
            if (m < M) {
                const float* ap = &A[(size_t)m * K + k0 + ak];
                a0 = *reinterpret_cast<const float4*>(ap);
                a1 = *reinterpret_cast<const float4*>(ap + 4);
            }
            bv = *reinterpret_cast<const float4*>(&B[(size_t)(k0 + brow) * Ncol + nBase + bcol]);
        }
        #pragma unroll
        for (int k = 0; k < 16; k++) {
            float4 a = *reinterpret_cast<const float4*>(&As[buf][k][lane * 4]);
            longlong2 b01 = *reinterpret_cast<const longlong2*>(&Bs[buf][k][cg * 4]);
            longlong2 b23 = *reinterpret_cast<const longlong2*>(&Bs[buf][k][cg * 4 + 2]);
            ull bp[4] = {(ull)b01.x, (ull)b01.y, (ull)b23.x, (ull)b23.y};
            ull ad[4] = {pack2(a.x, a.x), pack2(a.y, a.y), pack2(a.z, a.z), pack2(a.w, a.w)};
            #pragma unroll
            for (int e = 0; e < 4; e++)
                #pragma unroll
                for (int j = 0; j < 4; j++) fma2(acc[e][j], ad[e], bp[j]);
        }
        __syncthreads();
    }

    float bs[8] = {0, 0, 0, 0, 0, 0, 0, 0};
    if (bias) {
        float4 t0 = *reinterpret_cast<const float4*>(&bias[nBase + cg * 8]);
        float4 t1 = *reinterpret_cast<const float4*>(&bias[nBase + cg * 8 + 4]);
        bs[0] = t0.x; bs[1] = t0.y; bs[2] = t0.z; bs[3] = t0.w;
        bs[4] = t1.x; bs[5] = t1.y; bs[6] = t1.z; bs[7] = t1.w;
    }
    #pragma unroll
    for (int e = 0; e < 4; e++) {
        int mm = mBase + lane * 4 + e;
        if (mm < M) {
            float v[8];
            #pragma unroll
            for (int j = 0; j < 4; j++) unpack2(acc[e][j], v[2 * j], v[2 * j + 1]);
            float* cp = &Cout[(size_t)mm * Ncol + nBase + cg * 8];
            *reinterpret_cast<float4*>(cp) =
                make_float4(v[0] + bs[0], v[1] + bs[1], v[2] + bs[2], v[3] + bs[3]);
            *reinterpret_cast<float4*>(cp + 4) =
                make_float4(v[4] + bs[4], v[5] + bs[5], v[6] + bs[6], v[7] + bs[7]);
        }
    }
}

// m = x @ W
__global__ void __launch_bounds__(256) gemm_m(const float* __restrict__ x,
                                              const float* __restrict__ W, int M) {
    gemm_core16(x, W, nullptr, g_m, M, 64, 64, blockIdx.y * 128, 0);
}

// p1/p2 = m @ Wpre[0:64]/[64:128]  (blockIdx.x selects)
__global__ void __launch_bounds__(256) gemm_p12(const float* __restrict__ Wpre, int M) {
    const float* B = Wpre + blockIdx.x * 64 * 64;
    float* C = blockIdx.x ? g_p2 : g_p1;
    gemm_core16(g_m, B, nullptr, C, M, 64, 64, blockIdx.y * 128, 0);
}

// gi = out_node @ Wih + bih ; gh = x @ Whh + bhh  (blockIdx.z selects)
__global__ void __launch_bounds__(256) gemm_gigh(const float* __restrict__ x,
                                                 const float* __restrict__ Wih,
                                                 const float* __restrict__ bih,
                                                 const float* __restrict__ Whh,
                                                 const float* __restrict__ bhh, int M) {
    const float* A = blockIdx.z ? x : g_out_node;
    const float* B = blockIdx.z ? Whh : Wih;
    const float* bias = blockIdx.z ? bhh : bih;
    float* C = blockIdx.z ? g_gh : g_gi;
    gemm_core16(A, B, bias, C, M, 192, 64, blockIdx.y * 128, blockIdx.x * 64);
}

// ---------------- fused edge compute + node reduce: 2 warps per node ----------------
__global__ void __launch_bounds__(256) node_edge_reduce(const float* __restrict__ bpre,
                                                        int N) {
    int gw = blockIdx.x * 8 + (threadIdx.x >> 5);
    int n = gw >> 1;
    int half = gw & 1;
    if (n >= N) return;
    int lane = threadIdx.x & 31;
    int ch = half * 32 + lane;

    int off0 = g_off[n], off1 = g_off[n + 1];
    int deg = off1 - off0;

    float base = g_p1[(size_t)n * 64 + ch] + g_c3[ch];
    float c30 = g_C3[ch], c31 = g_C3[64 + ch], c32 = g_C3[128 + ch];
    float bp = bpre[ch];

    float s1 = 0.f, s2 = 0.f;
    float mn = 3.4e38f, mx = -3.4e38f;

    int src1 = 0;
    float4 at0 = make_float4(0.f, 0.f, 0.f, 0.f), at1 = at0;
    float va0 = 0.f;
    if (deg > 0) {
        int s0 = g_srcp[off0];
        at0 = g_attrp[off0];
        va0 = g_p2[(size_t)s0 * 64 + ch];
    }
    if (deg > 1) {
        src1 = g_srcp[off0 + 1];
        at1 = g_attrp[off0 + 1];
    }
    for (int i = off0; i < off1; i++) {
        float va = va0;
        float4 at = at0;
        if (i + 1 < off1) {
            va0 = g_p2[(size_t)src1 * 64 + ch];
            at0 = at1;
            if (i + 2 < off1) {
                src1 = g_srcp[i + 2];
                at1 = g_attrp[i + 2];
            }
        }
        float h = at.w * (base + va + at.x * c30 + at.y * c31 + at.z * c32) + bp;
        s1 += h; s2 += h * h;
        mn = fminf(mn, h); mx = fmaxf(mx, h);
    }

    float cnt = (float)deg;
    float safe = fmaxf(cnt, 1.f);
    float inv = 1.f / safe;
    float mean = s1 * inv;
    float stdv = sqrtf(fmaxf(s2 * inv - mean * mean, 0.f) + 1e-5f);
    if (deg == 0) { mn = 0.f; mx = 0.f; }
    size_t b = (size_t)n * 256 + ch;
    g_agg[b]       = mean;
    g_agg[b + 64]  = mn;
    g_agg[b + 128] = mx;
    g_agg[b + 192] = stdv;
    if (ch == 0) {
        float avg = g_avgsum[0] / (float)N;
        float logd = logf(safe + 1.f);
        float a = logd / avg;
        g_a[n]  = a;
        g_ia[n] = a * (avg / logd);   // fp-composed o3 scale
    }
}

// ---------------- Wpost GEMM (K=832), on-the-fly z, BK=16 double-buffered ----------------
__global__ void __launch_bounds__(256) gemm_post(const float* __restrict__ Wpost,
                                                 const float* __restrict__ bpost, int M) {
    __shared__ float As[2][16][128];
    __shared__ ull   Bs[2][16][32];
    int tid = threadIdx.x;
    int lane = tid & 31;
    int cg = tid >> 5;
    int mBase = blockIdx.x * 128;
    ull acc[4][4];
    #pragma unroll
    for (int e = 0; e < 4; e++)
        #pragma unroll
        for (int j = 0; j < 4; j++) acc[e][j] = 0ull;

    int ar = tid & 127;
    int ak = (tid >> 7) * 8;
    int brow = tid / 16;
    int bp_idx = (tid % 16) * 2;
    int bcol = (tid % 16) * 4;
    int m = mBase + ar;
    float sa = 0.f, sia = 0.f;
    if (m < M) { sa = g_a[m]; sia = g_ia[m]; }

    float4 a0 = make_float4(0.f, 0.f, 0.f, 0.f), a1 = a0;
    if (m < M) {
        #pragma unroll
        for (int q = 0; q < 2; q++) {
            int k = ak + q * 4;
            float sc = 1.f;
            const float* src;
            if (k < 64)       src = &g_m[(size_t)m * 64 + k];
            else if (k < 320) src = &g_agg[(size_t)m * 256 + (k - 64)];
            else if (k < 576) { src = &g_agg[(size_t)m * 256 + (k - 320)]; sc = sa; }
            else              { src = &g_agg[(size_t)m * 256 + (k - 576)]; sc = sia; }
            float4 av = *reinterpret_cast<const float4*>(src);
            av.x *= sc; av.y *= sc; av.z *= sc; av.w *= sc;
            if (q == 0) a0 = av; else a1 = av;
        }
    }
    float4 bv = *reinterpret_cast<const float4*>(&Wpost[(size_t)brow * 64 + bcol]);

    const int nk = 832 / 16;
    #pragma unroll 1
    for (int it = 0; it < nk; it++) {
        int buf = it & 1;
        As[buf][ak + 0][ar] = a0.x; As[buf][ak + 1][ar] = a0.y;
        As[buf][ak + 2][ar] = a0.z; As[buf][ak + 3][ar] = a0.w;
        As[buf][ak + 4][ar] = a1.x; As[buf][ak + 5][ar] = a1.y;
        As[buf][ak + 6][ar] = a1.z; As[buf][ak + 7][ar] = a1.w;
        Bs[buf][brow][bp_idx]     = pack2(bv.x, bv.y);
        Bs[buf][brow][bp_idx + 1] = pack2(bv.z, bv.w);
        __syncthreads();
        if (it + 1 < nk) {
            int k0 = (it + 1) * 16;
            a0 = make_float4(0.f, 0.f, 0.f, 0.f); a1 = a0;
            if (m < M) {
                #pragma unroll
                for (int q = 0; q < 2; q++) {
                    int k = k0 + ak + q * 4;
                    float sc = 1.f;
                    const float* src;
                    if (k < 64)       src = &g_m[(size_t)m * 64 + k];
                    else if (k < 320) src = &g_agg[(size_t)m * 256 + (k - 64)];
                    else if (k < 576) { src = &g_agg[(size_t)m * 256 + (k - 320)]; sc = sa; }
                    else              { src = &g_agg[(size_t)m * 256 + (k - 576)]; sc = sia; }
                    float4 av = *reinterpret_cast<const float4*>(src);
                    av.x *= sc; av.y *= sc; av.z *= sc; av.w *= sc;
                    if (q == 0) a0 = av; else a1 = av;
                }
            }
            bv = *reinterpret_cast<const float4*>(&Wpost[(size_t)(k0 + brow) * 64 + bcol]);
        }
        #pragma unroll
        for (int k = 0; k < 16; k++) {
            float4 a = *reinterpret_cast<const float4*>(&As[buf][k][lane * 4]);
            longlong2 b01 = *reinterpret_cast<const longlong2*>(&Bs[buf][k][cg * 4]);
            longlong2 b23 = *reinterpret_cast<const longlong2*>(&Bs[buf][k][cg * 4 + 2]);
            ull bp4[4] = {(ull)b01.x, (ull)b01.y, (ull)b23.x, (ull)b23.y};
            ull ad[4] = {pack2(a.x, a.x), pack2(a.y, a.y), pack2(a.z, a.z), pack2(a.w, a.w)};
            #pragma unroll
            for (int e = 0; e < 4; e++)
                #pragma unroll
                for (int j = 0; j < 4; j++) fma2(acc[e][j], ad[e], bp4[j]);
        }
        __syncthreads();
    }

    float4 t0 = *reinterpret_cast<const float4*>(&bpost[cg * 8]);
    float4 t1 = *reinterpret_cast<const float4*>(&bpost[cg * 8 + 4]);
    float bs[8] = {t0.x, t0.y, t0.z, t0.w, t1.x, t1.y, t1.z, t1.w};
    #pragma unroll
    for (int e = 0; e < 4; e++) {
        int mm = mBase + lane * 4 + e;
        if (mm < M) {
            float v[8];
            #pragma unroll
            for (int j = 0; j < 4; j++) unpack2(acc[e][j], v[2 * j], v[2 * j + 1]);
            float* cp = &g_out_node[(size_t)mm * 64 + cg * 8];
            *reinterpret_cast<float4*>(cp) =
                make_float4(v[0] + bs[0], v[1] + bs[1], v[2] + bs[2], v[3] + bs[3]);
            *reinterpret_cast<float4*>(cp + 4) =
                make_float4(v[4] + bs[4], v[5] + bs[5], v[6] + bs[6], v[7] + bs[7]);
        }
    }
}

// ---------------- GRU elementwise ----------------
__global__ void gru_kernel(const float* __restrict__ x, float* __restrict__ out, int N) {
    int idx = blockIdx.x * 256 + threadIdx.x;
    if (idx >= N * CC) return;
    int n = idx >> 6, c = idx & 63;
    size_t b = (size_t)n * 192;
    float ir = g_gi[b + c],        hr = g_gh[b + c];
    float iz = g_gi[b + 64 + c],   hz = g_gh[b + 64 + c];
    float in_ = g_gi[b + 128 + c], hn = g_gh[b + 128 + c];
    float r = 1.f / (1.f + expf(-(ir + hr)));
    float z = 1.f / (1.f + expf(-(iz + hz)));
    float nn = tanhf(in_ + r * hn);
    out[idx] = (1.f - z) * nn + z * x[idx];
}

// ---------------- launch ----------------
extern "C" void kernel_launch(void* const* d_in, const int* in_sizes, int n_in,
                              void* d_out, int out_size) {
    const float* x         = (const float*)d_in[0];
    const float* edge_attr = (const float*)d_in[1];
    const float* deg_hist  = (const float*)d_in[2];
    const float* W         = (const float*)d_in[3];
    const float* We        = (const float*)d_in[4];
    const float* be        = (const float*)d_in[5];
    const float* Wpre      = (const float*)d_in[6];
    const float* bpre      = (const float*)d_in[7];
    const float* Wpost     = (const float*)d_in[8];
    const float* bpost     = (const float*)d_in[9];
    const float* Wih       = (const float*)d_in[10];
    const float* bih       = (const float*)d_in[11];
    const float* Whh       = (const float*)d_in[12];
    const float* bhh       = (const float*)d_in[13];
    const int*   edge_index = (const int*)d_in[14];

    int N = in_sizes[0] / CC;
    int E = in_sizes[14] / 2;

    int nodeElems = N * CC;
    int mBlocks = (N + 127) / 128;
    int eBlocks256 = (E + 255) / 256;

    init_kernel<<<(N + 255) / 256, 256>>>(N);
    avglog_kernel<<<(N + 255) / 256, 256>>>(deg_hist, N);
    count_kernel<<<eBlocks256, 256>>>(edge_index, E);
    gemm_m<<<dim3(1, mBlocks), 256>>>(x, W, N);                 // 4th launch -> ncu slot
    prep_kernel<<<1, 256>>>(We, be, Wpre);
    scan_kernel<<<1, 1024>>>(N, E);
    scatter_kernel<<<eBlocks256, 256>>>(edge_index, edge_attr, E);
    gemm_p12<<<dim3(2, mBlocks), 256>>>(Wpre, N);
    node_edge_reduce<<<(2 * N + 7) / 8, 256>>>(bpre, N);
    gemm_post<<<mBlocks, 256>>>(Wpost, bpost, N);
    gemm_gigh<<<dim3(3, mBlocks, 2), 256>>>(x, Wih, bih, Whh, bhh, N);
    gru_kernel<<<(nodeElems + 255) / 256, 256>>>(x, (float*)d_out, N);
}